// round 2
// baseline (speedup 1.0000x reference)
#include <cuda_runtime.h>
#include <math.h>

#define NCLS 19
#define DD   128
#define HWP  65536          // H*W
#define BB   8
#define NPIX (BB*HWP)       // 524288

// ---- static scratch (no allocations allowed) ----
__device__ float          g_sums[NCLS*DD];
__device__ float          g_means[NCLS*DD];
__device__ int            g_cnt[NCLS];
__device__ float          g_var[NCLS];
__device__ unsigned char  g_labs[NPIX];

// ---------------------------------------------------------------- zero
__global__ void k_zero() {
    int t = blockIdx.x*blockDim.x + threadIdx.x;
    if (t < NCLS*DD) g_sums[t] = 0.f;
    if (t < NCLS) { g_cnt[t] = 0; g_var[t] = 0.f; }
}

// ------------------------------------------------------ label pack + hist
__global__ void __launch_bounds__(256) k_prep(const int* __restrict__ labels) {
    __shared__ int hist[NCLS];
    int t = threadIdx.x;
    if (t < NCLS) hist[t] = 0;
    __syncthreads();
    int p = blockIdx.x*256 + t;
    int lab = labels[p];
    unsigned char u = (lab >= 0 && lab < NCLS) ? (unsigned char)lab : (unsigned char)255;
    g_labs[p] = u;
    if (u < NCLS) atomicAdd(&hist[u], 1);
    __syncthreads();
    if (t < NCLS) atomicAdd(&g_cnt[t], hist[t]);
}

// ---------------------------------------------------------------- pass 1
// Each thread owns a fixed d-pair (d0, d0+1); label is shared by both dims,
// so one predicated packed f32x2 add covers 2 elements per class test.
__device__ __forceinline__ unsigned long long packf2(float lo, float hi) {
    unsigned long long v;
    asm("mov.b64 %0, {%1, %2};" : "=l"(v) : "f"(lo), "f"(hi));
    return v;
}

template<int CI>
__device__ __forceinline__ void step_all(unsigned long long* acc, unsigned long long v, int lab) {
    asm volatile("{\n\t.reg .pred p;\n\tsetp.eq.s32 p, %1, %2;\n\t@p add.rn.f32x2 %0, %0, %3;\n\t}"
        : "+l"(acc[CI]) : "r"(lab), "n"(CI), "l"(v));
    if constexpr (CI + 1 < NCLS) step_all<CI+1>(acc, v, lab);
}

__global__ void __launch_bounds__(256) k_pass1(const float* __restrict__ feats) {
    int jp = blockIdx.x;            // d-pair index 0..63
    int b  = blockIdx.y;            // batch plane 0..7
    int d0 = jp * 2;
    const float4* fA = (const float4*)(feats + ((size_t)b*DD + d0    ) * HWP);
    const float4* fB = (const float4*)(feats + ((size_t)b*DD + d0 + 1) * HWP);
    const uchar4* lb = (const uchar4*)(g_labs + (size_t)b*HWP);

    unsigned long long acc[NCLS];
    #pragma unroll
    for (int c = 0; c < NCLS; c++) acc[c] = 0ull;

    const int nvec = HWP / 4;       // 16384 float4 per plane row-set
    for (int i = threadIdx.x; i < nvec; i += 256) {
        float4 a  = fA[i];
        float4 bb = fB[i];
        uchar4 l  = lb[i];
        step_all<0>(acc, packf2(a.x, bb.x), (int)l.x);
        step_all<0>(acc, packf2(a.y, bb.y), (int)l.y);
        step_all<0>(acc, packf2(a.z, bb.z), (int)l.z);
        step_all<0>(acc, packf2(a.w, bb.w), (int)l.w);
    }

    // block reduce: warp shuffle -> shared -> 38 global atomics
    __shared__ float shred[2*NCLS];
    if (threadIdx.x < 2*NCLS) shred[threadIdx.x] = 0.f;
    __syncthreads();
    int lane = threadIdx.x & 31;
    #pragma unroll
    for (int c = 0; c < NCLS; c++) {
        float x, y;
        asm("mov.b64 {%0, %1}, %2;" : "=f"(x), "=f"(y) : "l"(acc[c]));
        #pragma unroll
        for (int o = 16; o; o >>= 1) {
            x += __shfl_down_sync(0xffffffffu, x, o);
            y += __shfl_down_sync(0xffffffffu, y, o);
        }
        if (lane == 0) {
            atomicAdd(&shred[2*c],   x);
            atomicAdd(&shred[2*c+1], y);
        }
    }
    __syncthreads();
    if (threadIdx.x < 2*NCLS) {
        int c = threadIdx.x >> 1, bit = threadIdx.x & 1;
        atomicAdd(&g_sums[c*DD + d0 + bit], shred[threadIdx.x]);
    }
}

// ---------------------------------------------------------------- means
__global__ void k_means() {
    int t = blockIdx.x*blockDim.x + threadIdx.x;
    if (t < NCLS*DD) {
        int c = t >> 7;
        g_means[t] = g_sums[t] / fmaxf((float)g_cnt[c], 1.f);
    }
}

// ---------------------------------------------------------------- pass 2
// Per-pixel hinged distance to own class mean. Means in shared with stride
// 129 (129 % 32 == 1) -> distinct labels hit distinct banks, same label
// broadcasts: conflict-free.
__global__ void __launch_bounds__(256) k_pass2(const float* __restrict__ feats) {
    __shared__ float ms[NCLS*129];
    __shared__ float vs[NCLS];
    int t = threadIdx.x;
    for (int i = t; i < NCLS*DD; i += 256)
        ms[(i >> 7)*129 + (i & 127)] = g_means[i];
    if (t < NCLS) vs[t] = 0.f;
    __syncthreads();

    int p  = blockIdx.x*256 + t;
    int b  = p >> 16;
    int hw = p & 65535;
    const float* fp = feats + (size_t)b*DD*HWP + hw;
    int lab = g_labs[p];
    if (lab < NCLS) {
        const float* mrow = ms + lab*129;
        float acc = 0.f;
        #pragma unroll 16
        for (int d = 0; d < DD; d++) {
            float diff = fp[(size_t)d*HWP] - mrow[d];
            acc = fmaf(diff, diff, acc);
        }
        float h = fmaxf(sqrtf(acc) - 0.5f, 0.f);   // DELTA_V = 0.5
        atomicAdd(&vs[lab], h*h);
    }
    __syncthreads();
    if (t < NCLS) atomicAdd(&g_var[t], vs[t]);
}

// ---------------------------------------------------------------- final
__global__ void __launch_bounds__(512) k_final(float* __restrict__ out) {
    __shared__ float vld[NCLS];
    __shared__ float sreg[NCLS];
    __shared__ float spair[NCLS*NCLS];
    int t = threadIdx.x;
    if (t < NCLS) vld[t] = (g_cnt[t] > 100) ? 1.f : 0.f;   // MAX_VIEWS = 100, strict >
    if (t < NCLS) {
        float s = 0.f;
        for (int d = 0; d < DD; d++) { float m = g_means[t*DD + d]; s = fmaf(m, m, s); }
        sreg[t] = (s > 0.f) ? sqrtf(s) : 0.f;
    }
    if (t < NCLS*NCLS) {
        int a = t / NCLS, b2 = t % NCLS;
        float s = 0.f;
        for (int d = 0; d < DD; d++) {
            float diff = g_means[a*DD + d] - g_means[b2*DD + d];
            s = fmaf(diff, diff, s);
        }
        float pdn = (s > 0.f) ? sqrtf(s) : 0.f;
        float hd  = fmaxf(2.f*1.5f - pdn, 0.f);    // 2*DELTA_D
        spair[t] = hd*hd;
    }
    __syncthreads();
    if (t == 0) {
        int last = -1;
        for (int c = 0; c < NCLS; c++) if (vld[c] > 0.f) last = c;
        float tc = 0.f, lvar = 0.f, lreg = 0.f, ldist = 0.f;
        for (int c = 0; c < NCLS; c++) {
            if (vld[c] > 0.f) {
                tc   += 1.f;
                lvar += g_var[c] / fmaxf((float)g_cnt[c], 1.f);
                lreg += sreg[c];
            }
        }
        // faithful buggy double loop: a over all valid, b over valid except
        // the LAST valid class id; includes a == b pairs.
        for (int a = 0; a < NCLS; a++)
            for (int b2 = 0; b2 < NCLS; b2++)
                if (vld[a] > 0.f && vld[b2] > 0.f && b2 != last)
                    ldist += spair[a*NCLS + b2];
        out[0] = lvar/tc + ldist/(tc*(tc - 1.f)) + 0.001f*lreg/tc;  // ALPHA=BETA=1, GAMMA=1e-3
    }
}

// ---------------------------------------------------------------- launch
extern "C" void kernel_launch(void* const* d_in, const int* in_sizes, int n_in,
                              void* d_out, int out_size) {
    const float* feats  = (const float*)d_in[0];
    const int*   labels = (const int*)d_in[1];
    float* out = (float*)d_out;

    k_zero <<<(NCLS*DD + 255)/256, 256>>>();
    k_prep <<<NPIX/256, 256>>>(labels);
    k_pass1<<<dim3(64, 8), 256>>>(feats);
    k_means<<<(NCLS*DD + 255)/256, 256>>>();
    k_pass2<<<NPIX/256, 256>>>(feats);
    k_final<<<1, 512>>>(out);
}